// round 7
// baseline (speedup 1.0000x reference)
#include <cuda_runtime.h>
#include <cuda_bf16.h>
#include <cstdint>

// Problem constants (fixed by the dataset)
#define BB 16
#define TT 512
#define DD 384
#define D4 (DD / 4)          // 96 float4 per row
#define MAXLEN 4096
#define FPB 32               // frames per block
#define CPB (MAXLEN / FPB)   // 128 chunks (blocks) per batch
#define NTHR 512
#define NWARP (NTHR / 32)    // 16
#define TILE_BYTES (FPB * DD * 4)   // 49152 = 48KB staging tile

// ---------------------------------------------------------------------------
// Fused kernel:
//  - warp-shuffle inclusive scan of durations (proven R5)
//  - scatter inversion (proven R4/R5): token t owns [cum[t-1], min(cum[t],lim))
//  - gather into 48KB smem staging tile (STS instead of STG)
//  - ONE 1D cp.async.bulk shared->global per block: TMA drives the 100MB
//    store stream, bypassing per-thread STG.128 LSU issue cost (12 cyc each).
// blockIdx.x = b * CPB + chunk; block covers frames [chunk*FPB, chunk*FPB+FPB)
// ---------------------------------------------------------------------------
__global__ void __launch_bounds__(NTHR)
lr_fused(const float4* __restrict__ x, const int* __restrict__ dur,
         float* __restrict__ out, int mode) {
    extern __shared__ float4 tile[];     // FPB*D4 = 3072 float4 = 48KB
    __shared__ int wsum[NWARP];
    __shared__ int fidx[FPB];
    __shared__ int s_mel;

    const int b     = blockIdx.x / CPB;
    const int chunk = blockIdx.x - b * CPB;
    const int t     = threadIdx.x;
    const int lane  = t & 31;
    const int w     = t >> 5;

    // ---- inclusive scan of durations: warp shuffle + warp-total fixup ----
    const int v = __ldg(&dur[b * TT + t]);
    int sc = v;
    #pragma unroll
    for (int o = 1; o < 32; o <<= 1) {
        int n = __shfl_up_sync(0xffffffffu, sc, o);
        if (lane >= o) sc += n;
    }
    if (lane == 31) wsum[w] = sc;
    if (t < FPB) fidx[t] = -1;
    __syncthreads();
    if (w == 0 && lane < NWARP) {
        int ws = wsum[lane];
        #pragma unroll
        for (int o = 1; o < NWARP; o <<= 1) {
            int n = __shfl_up_sync(0x0000ffffu, ws, o);
            if (lane >= o) ws += n;
        }
        wsum[lane] = ws;
        if (lane == NWARP - 1) s_mel = ws;   // total = mel_len
    }
    __syncthreads();

    const int end   = sc + (w ? wsum[w - 1] : 0);   // inclusive cum[t]
    const int start = end - v;                       // cum[t-1]
    const int mel   = s_mel;
    const int lim   = mel < MAXLEN ? mel : MAXLEN;
    const int f0    = chunk * FPB;

    // ---- scatter inversion into this block's window (proven semantics) ----
    {
        const int e2 = end < lim ? end : lim;
        int a  = start > f0 ? start : f0;
        int bd = e2 < (f0 + FPB) ? e2 : (f0 + FPB);
        for (int f = a; f < bd; ++f) fidx[f - f0] = t;        // durations < 8
    }

    // mel_len tail (output 1), written once per batch by chunk 0
    if (chunk == 0 && t == 0 && mode) {
        const long long base = (long long)BB * MAXLEN * DD;
        if (mode == 1)      out[base + b] = (float)mel;
        else                ((long long*)(out + base))[b] = (long long)mel;
    }
    __syncthreads();

    // ---- gather into smem staging tile: FPB*96 = 3072 float4, 6/thread ----
    const float4* xb = x + (size_t)b * TT * D4;
    #pragma unroll
    for (int k = 0; k < (FPB * D4) / NTHR; ++k) {
        const int g  = t + k * NTHR;
        const int fl = g / D4;
        const int d4 = g - fl * D4;
        const int id = fidx[fl];
        float4 val = make_float4(0.f, 0.f, 0.f, 0.f);
        if (id >= 0) val = __ldg(&xb[id * D4 + d4]);
        tile[g] = val;
    }
    __syncthreads();

    // ---- one 1D bulk async store: smem tile -> contiguous GMEM window ----
    if (t == 0) {
        asm volatile("fence.proxy.async.shared::cta;" ::: "memory");
        uint32_t saddr;
        asm("{ .reg .u64 tmp; cvta.to.shared.u64 tmp, %1; cvt.u32.u64 %0, tmp; }"
            : "=r"(saddr) : "l"(tile));
        float* gdst = out + ((size_t)b * MAXLEN + f0) * DD;
        asm volatile(
            "cp.async.bulk.global.shared::cta.bulk_group [%0], [%1], %2;"
            :: "l"(gdst), "r"(saddr), "r"((uint32_t)TILE_BYTES)
            : "memory");
        asm volatile("cp.async.bulk.commit_group;" ::: "memory");
        asm volatile("cp.async.bulk.wait_group.read 0;" ::: "memory");
    }
}

extern "C" void kernel_launch(void* const* d_in, const int* in_sizes, int n_in,
                              void* d_out, int out_size) {
    const float* x   = (const float*)d_in[0];
    const int*   dur = (const int*)d_in[1];   // int32 (JAX x64 disabled)

    // Opt-in for >48KB dynamic smem (48KB tile + static smem headroom).
    // Host-side attribute call: not a stream op, not an allocation; the first
    // (correctness) call configures it before graph capture ever starts.
    cudaFuncSetAttribute(lr_fused, cudaFuncAttributeMaxDynamicSharedMemorySize,
                         TILE_BYTES);

    const long long base = (long long)BB * MAXLEN * DD;   // 25,165,824 f32
    int mode = 0;
    if ((long long)out_size == base + BB)            mode = 1;  // mel as f32
    else if ((long long)out_size == base + 2 * BB)   mode = 2;  // mel as i64

    lr_fused<<<BB * CPB, NTHR, TILE_BYTES>>>((const float4*)x, dur,
                                             (float*)d_out, mode);
}

// round 8
// speedup vs baseline: 1.5322x; 1.5322x over previous
#include <cuda_runtime.h>
#include <cuda_bf16.h>

// Problem constants (fixed by the dataset)
#define BB 16
#define TT 512
#define DD 384
#define D4 (DD / 4)          // 96 float4 per row
#define MAXLEN 4096
#define NTHR 512
#define NWARP (NTHR / 32)    // 16
#define FPBLK 128            // frames per block (coarsened)
#define BPB (MAXLEN / FPBLK) // 32 blocks per batch -> grid = 512 = ONE wave

// ---------------------------------------------------------------------------
// Fused, block-coarsened kernel (single resident wave, 512 blocks):
//  - warp-shuffle inclusive scan of durations, ONCE per block (proven R5 code)
//  - scatter inversion (proven): token t owns [cum[t-1], min(cum[t],lim)),
//    windowed to this block's 128 frames
//  - gather + streaming float4 stores (proven R5 path), 24 float4/thread
// blockIdx.x = b * BPB + blk; block covers frames [blk*FPBLK, blk*FPBLK+FPBLK)
// ---------------------------------------------------------------------------
__global__ void __launch_bounds__(NTHR)
lr_fused(const float4* __restrict__ x, const int* __restrict__ dur,
         float* __restrict__ out, int mode) {
    __shared__ int wsum[NWARP];
    __shared__ int fidx[FPBLK];   // frame -> token index for this window, -1 = zero
    __shared__ int s_mel;

    const int b    = blockIdx.x / BPB;
    const int blk  = blockIdx.x - b * BPB;
    const int t    = threadIdx.x;
    const int lane = t & 31;
    const int w    = t >> 5;

    // ---- inclusive scan of durations: warp shuffle + warp-total fixup ----
    const int v = __ldg(&dur[b * TT + t]);
    int sc = v;
    #pragma unroll
    for (int o = 1; o < 32; o <<= 1) {
        int n = __shfl_up_sync(0xffffffffu, sc, o);
        if (lane >= o) sc += n;
    }
    if (lane == 31) wsum[w] = sc;
    // init window map to -1 (zero-fill frames)
    if (t < FPBLK) fidx[t] = -1;
    __syncthreads();
    if (w == 0 && lane < NWARP) {
        int ws = wsum[lane];
        #pragma unroll
        for (int o = 1; o < NWARP; o <<= 1) {
            int n = __shfl_up_sync(0x0000ffffu, ws, o);
            if (lane >= o) ws += n;
        }
        wsum[lane] = ws;
        if (lane == NWARP - 1) s_mel = ws;   // total = mel_len
    }
    __syncthreads();

    const int end   = sc + (w ? wsum[w - 1] : 0);   // inclusive cum[t]
    const int start = end - v;                       // cum[t-1]
    const int mel   = s_mel;
    const int lim   = mel < MAXLEN ? mel : MAXLEN;
    const int f0    = blk * FPBLK;

    // ---- scatter inversion into this block's 128-frame window ----
    {
        const int e2 = end < lim ? end : lim;
        int a  = start > f0 ? start : f0;
        int bd = e2 < (f0 + FPBLK) ? e2 : (f0 + FPBLK);
        for (int f = a; f < bd; ++f) fidx[f - f0] = t;        // durations < 8
    }

    // mel_len tail (output 1), written once per batch by block 0
    if (blk == 0 && t == 0 && mode) {
        const long long base = (long long)BB * MAXLEN * DD;
        if (mode == 1)      out[base + b] = (float)mel;
        else                ((long long*)(out + base))[b] = (long long)mel;
    }
    __syncthreads();

    // ---- gather + streaming store: FPBLK*96 = 12288 float4, 24/thread ----
    const float4* xb = x + (size_t)b * TT * D4;
    float4* ob = (float4*)((float*)out) + ((size_t)b * MAXLEN + f0) * D4;
    #pragma unroll
    for (int k = 0; k < (FPBLK * D4) / NTHR; ++k) {
        const int g  = t + k * NTHR;      // contiguous, fully coalesced
        const int fl = g / D4;
        const int d4 = g - fl * D4;
        const int id = fidx[fl];
        float4 val = make_float4(0.f, 0.f, 0.f, 0.f);
        if (id >= 0) val = __ldg(&xb[id * D4 + d4]);
        __stcs(&ob[g], val);
    }
}

extern "C" void kernel_launch(void* const* d_in, const int* in_sizes, int n_in,
                              void* d_out, int out_size) {
    const float* x   = (const float*)d_in[0];
    const int*   dur = (const int*)d_in[1];   // int32 (JAX x64 disabled)

    const long long base = (long long)BB * MAXLEN * DD;   // 25,165,824 f32
    int mode = 0;
    if ((long long)out_size == base + BB)            mode = 1;  // mel as f32
    else if ((long long)out_size == base + 2 * BB)   mode = 2;  // mel as i64

    lr_fused<<<BB * BPB, NTHR>>>((const float4*)x, dur, (float*)d_out, mode);
}

// round 9
// speedup vs baseline: 1.6349x; 1.0671x over previous
#include <cuda_runtime.h>
#include <cuda_bf16.h>

// Problem constants (fixed by the dataset)
#define BB 16
#define TT 512
#define DD 384
#define D4 (DD / 4)          // 96 float4 per row
#define MAXLEN 4096
#define NTHR 512
#define NWARP (NTHR / 32)    // 16
#define FPBLK 64             // frames per block
#define BPB (MAXLEN / FPBLK) // 64 blocks per batch -> grid = 1024
#define F4PT ((FPBLK * D4) / NTHR)   // 12 float4 per thread
#define BATCH 4              // load batch depth (MLP)

// ---------------------------------------------------------------------------
// Fused kernel, R8 logic with finer blocks + explicit 4-deep load batching:
//  - warp-shuffle inclusive scan of durations (proven)
//  - scatter inversion (proven): token t owns [cum[t-1], min(cum[t],lim))
//  - gather: 4 independent LDG.128 issued back-to-back, then 4 STG.128 (.cs)
// blockIdx.x = b * BPB + blk; block covers frames [blk*FPBLK, blk*FPBLK+FPBLK)
// ---------------------------------------------------------------------------
__global__ void __launch_bounds__(NTHR)
lr_fused(const float4* __restrict__ x, const int* __restrict__ dur,
         float* __restrict__ out, int mode) {
    __shared__ int wsum[NWARP];
    __shared__ int fidx[FPBLK];   // frame -> token index for this window, -1 = zero
    __shared__ int s_mel;

    const int b    = blockIdx.x / BPB;
    const int blk  = blockIdx.x - b * BPB;
    const int t    = threadIdx.x;
    const int lane = t & 31;
    const int w    = t >> 5;

    // ---- inclusive scan of durations: warp shuffle + warp-total fixup ----
    const int v = __ldg(&dur[b * TT + t]);
    int sc = v;
    #pragma unroll
    for (int o = 1; o < 32; o <<= 1) {
        int n = __shfl_up_sync(0xffffffffu, sc, o);
        if (lane >= o) sc += n;
    }
    if (lane == 31) wsum[w] = sc;
    if (t < FPBLK) fidx[t] = -1;
    __syncthreads();
    if (w == 0 && lane < NWARP) {
        int ws = wsum[lane];
        #pragma unroll
        for (int o = 1; o < NWARP; o <<= 1) {
            int n = __shfl_up_sync(0x0000ffffu, ws, o);
            if (lane >= o) ws += n;
        }
        wsum[lane] = ws;
        if (lane == NWARP - 1) s_mel = ws;   // total = mel_len
    }
    __syncthreads();

    const int end   = sc + (w ? wsum[w - 1] : 0);   // inclusive cum[t]
    const int start = end - v;                       // cum[t-1]
    const int mel   = s_mel;
    const int lim   = mel < MAXLEN ? mel : MAXLEN;
    const int f0    = blk * FPBLK;

    // ---- scatter inversion into this block's window (proven semantics) ----
    {
        const int e2 = end < lim ? end : lim;
        int a  = start > f0 ? start : f0;
        int bd = e2 < (f0 + FPBLK) ? e2 : (f0 + FPBLK);
        for (int f = a; f < bd; ++f) fidx[f - f0] = t;        // durations < 8
    }

    // mel_len tail (output 1), written once per batch by block 0
    if (blk == 0 && t == 0 && mode) {
        const long long base = (long long)BB * MAXLEN * DD;
        if (mode == 1)      out[base + b] = (float)mel;
        else                ((long long*)(out + base))[b] = (long long)mel;
    }
    __syncthreads();

    // ---- gather + streaming store: batched 4 LDG then 4 STG for MLP ----
    const float4* xb = x + (size_t)b * TT * D4;
    float4* ob = (float4*)((float*)out) + ((size_t)b * MAXLEN + f0) * D4;
    #pragma unroll
    for (int k0 = 0; k0 < F4PT; k0 += BATCH) {
        float4 val[BATCH];
        int    g[BATCH];
        #pragma unroll
        for (int j = 0; j < BATCH; ++j) {
            g[j] = t + (k0 + j) * NTHR;
            const int fl = g[j] / D4;
            const int d4 = g[j] - fl * D4;
            const int id = fidx[fl];
            val[j] = make_float4(0.f, 0.f, 0.f, 0.f);
            if (id >= 0) val[j] = __ldg(&xb[id * D4 + d4]);
        }
        #pragma unroll
        for (int j = 0; j < BATCH; ++j) {
            __stcs(&ob[g[j]], val[j]);
        }
    }
}

extern "C" void kernel_launch(void* const* d_in, const int* in_sizes, int n_in,
                              void* d_out, int out_size) {
    const float* x   = (const float*)d_in[0];
    const int*   dur = (const int*)d_in[1];   // int32 (JAX x64 disabled)

    const long long base = (long long)BB * MAXLEN * DD;   // 25,165,824 f32
    int mode = 0;
    if ((long long)out_size == base + BB)            mode = 1;  // mel as f32
    else if ((long long)out_size == base + 2 * BB)   mode = 2;  // mel as i64

    lr_fused<<<BB * BPB, NTHR>>>((const float4*)x, dur, (float*)d_out, mode);
}

// round 10
// speedup vs baseline: 1.7733x; 1.0846x over previous
#include <cuda_runtime.h>
#include <cuda_bf16.h>

// Problem constants (fixed by the dataset)
#define BB 16
#define TT 512
#define DD 384
#define D4 (DD / 4)          // 96 float4 per row
#define MAXLEN 4096
#define NTHR 512
#define NWARP (NTHR / 32)    // 16
#define FPBLK 64             // frames per block
#define BPB (MAXLEN / FPBLK) // 64 blocks per batch -> grid = 1024
#define F4PT ((FPBLK * D4) / NTHR)   // 12 float4 per thread
#define BATCH 6              // load batch depth (MLP): 2 batches of 6

// ---------------------------------------------------------------------------
// Fused kernel (R9 structure, MLP 4->6):
//  - warp-shuffle inclusive scan of durations (proven)
//  - scatter inversion (proven): token t owns [cum[t-1], min(cum[t],lim))
//  - gather: 6 independent LDG.128 issued back-to-back, then 6 STG.128 (.cs)
// blockIdx.x = b * BPB + blk; block covers frames [blk*FPBLK, blk*FPBLK+FPBLK)
// ---------------------------------------------------------------------------
__global__ void __launch_bounds__(NTHR)
lr_fused(const float4* __restrict__ x, const int* __restrict__ dur,
         float* __restrict__ out, int mode) {
    __shared__ int wsum[NWARP];
    __shared__ int fidx[FPBLK];   // frame -> token index for this window, -1 = zero
    __shared__ int s_mel;

    const int b    = blockIdx.x / BPB;
    const int blk  = blockIdx.x - b * BPB;
    const int t    = threadIdx.x;
    const int lane = t & 31;
    const int w    = t >> 5;

    // ---- inclusive scan of durations: warp shuffle + warp-total fixup ----
    const int v = __ldg(&dur[b * TT + t]);
    int sc = v;
    #pragma unroll
    for (int o = 1; o < 32; o <<= 1) {
        int n = __shfl_up_sync(0xffffffffu, sc, o);
        if (lane >= o) sc += n;
    }
    if (lane == 31) wsum[w] = sc;
    if (t < FPBLK) fidx[t] = -1;
    __syncthreads();
    if (w == 0 && lane < NWARP) {
        int ws = wsum[lane];
        #pragma unroll
        for (int o = 1; o < NWARP; o <<= 1) {
            int n = __shfl_up_sync(0x0000ffffu, ws, o);
            if (lane >= o) ws += n;
        }
        wsum[lane] = ws;
        if (lane == NWARP - 1) s_mel = ws;   // total = mel_len
    }
    __syncthreads();

    const int end   = sc + (w ? wsum[w - 1] : 0);   // inclusive cum[t]
    const int start = end - v;                       // cum[t-1]
    const int mel   = s_mel;
    const int lim   = mel < MAXLEN ? mel : MAXLEN;
    const int f0    = blk * FPBLK;

    // ---- scatter inversion into this block's window (proven semantics) ----
    {
        const int e2 = end < lim ? end : lim;
        int a  = start > f0 ? start : f0;
        int bd = e2 < (f0 + FPBLK) ? e2 : (f0 + FPBLK);
        for (int f = a; f < bd; ++f) fidx[f - f0] = t;        // durations < 8
    }

    // mel_len tail (output 1), written once per batch by block 0
    if (blk == 0 && t == 0 && mode) {
        const long long base = (long long)BB * MAXLEN * DD;
        if (mode == 1)      out[base + b] = (float)mel;
        else                ((long long*)(out + base))[b] = (long long)mel;
    }
    __syncthreads();

    // ---- gather + streaming store: 2 batches of 6 LDG then 6 STG (MLP=6) ----
    const float4* xb = x + (size_t)b * TT * D4;
    float4* ob = (float4*)((float*)out) + ((size_t)b * MAXLEN + f0) * D4;
    #pragma unroll
    for (int k0 = 0; k0 < F4PT; k0 += BATCH) {
        float4 val[BATCH];
        int    g[BATCH];
        #pragma unroll
        for (int j = 0; j < BATCH; ++j) {
            g[j] = t + (k0 + j) * NTHR;
            const int fl = g[j] / D4;
            const int d4 = g[j] - fl * D4;
            const int id = fidx[fl];
            val[j] = make_float4(0.f, 0.f, 0.f, 0.f);
            if (id >= 0) val[j] = __ldg(&xb[id * D4 + d4]);
        }
        #pragma unroll
        for (int j = 0; j < BATCH; ++j) {
            __stcs(&ob[g[j]], val[j]);
        }
    }
}

extern "C" void kernel_launch(void* const* d_in, const int* in_sizes, int n_in,
                              void* d_out, int out_size) {
    const float* x   = (const float*)d_in[0];
    const int*   dur = (const int*)d_in[1];   // int32 (JAX x64 disabled)

    const long long base = (long long)BB * MAXLEN * DD;   // 25,165,824 f32
    int mode = 0;
    if ((long long)out_size == base + BB)            mode = 1;  // mel as f32
    else if ((long long)out_size == base + 2 * BB)   mode = 2;  // mel as i64

    lr_fused<<<BB * BPB, NTHR>>>((const float4*)x, dur, (float*)d_out, mode);
}